// round 2
// baseline (speedup 1.0000x reference)
#include <cuda_runtime.h>
#include <math.h>

#define HW 128
#define NIMG 256            // 128 a-images + 128 b-images
#define KTOT 16384          // HW*HW
#define KSLICES 64          // split-K for gram
#define KPER 256            // K per slice

// ---- scratch (device globals: allocation-free) ----
__device__ float g_psd[NIMG * KTOT];          // per-image |FFT2|^2   (16 MB)
__device__ float g_gram[KSLICES * 128 * 128]; // split-K gram partials (4 MB)
__device__ float g_norm[256];                 // row squared norms (a then b)
__device__ float g_rowvals[128];              // diag log-prob per row
__device__ float g_psd_part[256];             // [0:128) sum(log avg), [128:256) sum(avg)

// =====================================================================
// 2D FFT (radix-2 DIF, no bit reversal: PSD stats are permutation-
// invariant) + |F|^2, one block per image.
// smem: 128 rows x pitch 129 float2 (conflict-free both passes) + 64 twiddles
// =====================================================================
#define FFT_SMEM ((128 * 129 + 64) * (int)sizeof(float2))

__global__ __launch_bounds__(256, 1)
void fft_psd_kernel(const float* __restrict__ x1, const float* __restrict__ x2) {
    extern __shared__ float2 sm[];
    float2* data = sm;                 // 128 * 129
    float2* tw   = sm + 128 * 129;     // 64 twiddles

    const int t   = threadIdx.x;       // 256 threads
    const int img = blockIdx.x;
    const float* src = (img < 128) ? (x1 + (size_t)img * KTOT)
                                   : (x2 + (size_t)(img - 128) * KTOT);

    if (t < 64) {
        float s, c;
        sincosf(-6.283185307179586f * (float)t * (1.0f / 128.0f), &s, &c);
        tw[t] = make_float2(c, s);
    }
    for (int idx = t; idx < KTOT; idx += 256) {
        data[(idx >> 7) * 129 + (idx & 127)] = make_float2(src[idx], 0.0f);
    }
    __syncthreads();

    const int line = t & 127;   // which row (pass 1) / column (pass 2)
    const int half = t >> 7;    // each line worked by 2 threads

    // ---- pass 1: row FFTs (stride 1) ----
    {
        float2* d = data + line * 129;
        for (int h = 64; h >= 1; h >>= 1) {
            const int tstep = 64 / h;
            #pragma unroll 4
            for (int bb = 0; bb < 32; ++bb) {
                int b = half * 32 + bb;
                int j = b & (h - 1);
                int p = ((b ^ j) << 1) + j;     // butterfly top index
                float2 u = d[p];
                float2 v = d[p + h];
                float2 w = tw[j * tstep];
                d[p] = make_float2(u.x + v.x, u.y + v.y);
                float dx = u.x - v.x, dy = u.y - v.y;
                d[p + h] = make_float2(dx * w.x - dy * w.y, dx * w.y + dy * w.x);
            }
            __syncthreads();
        }
    }
    // ---- pass 2: column FFTs (stride 129) ----
    {
        float2* d = data + line;
        for (int h = 64; h >= 1; h >>= 1) {
            const int tstep = 64 / h;
            #pragma unroll 4
            for (int bb = 0; bb < 32; ++bb) {
                int b = half * 32 + bb;
                int j = b & (h - 1);
                int p = ((b ^ j) << 1) + j;
                float2 u = d[p * 129];
                float2 v = d[(p + h) * 129];
                float2 w = tw[j * tstep];
                d[p * 129] = make_float2(u.x + v.x, u.y + v.y);
                float dx = u.x - v.x, dy = u.y - v.y;
                d[(p + h) * 129] = make_float2(dx * w.x - dy * w.y, dx * w.y + dy * w.x);
            }
            __syncthreads();
        }
    }

    float* dst = g_psd + (size_t)img * KTOT;
    for (int idx = t; idx < KTOT; idx += 256) {
        float2 v = data[(idx >> 7) * 129 + (idx & 127)];
        dst[idx] = v.x * v.x + v.y * v.y;
    }
}

// =====================================================================
// Row squared norms for a (rows 0..127) and b (rows 128..255)
// =====================================================================
__global__ __launch_bounds__(256)
void norm_kernel(const float* __restrict__ x1, const float* __restrict__ x2) {
    const int row = blockIdx.x;
    const float* src = (row < 128) ? (x1 + (size_t)row * KTOT)
                                   : (x2 + (size_t)(row - 128) * KTOT);
    float s = 0.0f;
    for (int k = threadIdx.x; k < KTOT; k += 256) {
        float v = src[k];
        s += v * v;
    }
    __shared__ float red[8];
    #pragma unroll
    for (int o = 16; o > 0; o >>= 1) s += __shfl_xor_sync(0xFFFFFFFFu, s, o);
    if ((threadIdx.x & 31) == 0) red[threadIdx.x >> 5] = s;
    __syncthreads();
    if (threadIdx.x == 0) {
        float tot = 0.0f;
        #pragma unroll
        for (int w = 0; w < 8; ++w) tot += red[w];
        g_norm[row] = tot;
    }
}

// =====================================================================
// Split-K Gram: G_part[ks][i][j] = sum_{k in slice ks} a[i][k]*b[j][k]
// grid (4, 64): 4 spatial 64x64 tiles, 64 K-slices of 256. 256 thr,
// 4x4 per-thread register tile, staged through smem in K-chunks of 32.
// =====================================================================
__global__ __launch_bounds__(256)
void gram_kernel(const float* __restrict__ A, const float* __restrict__ B) {
    __shared__ float As[32][65];
    __shared__ float Bs[32][65];
    const int i0 = (blockIdx.x & 1) * 64;
    const int j0 = (blockIdx.x >> 1) * 64;
    const int k0 = blockIdx.y * KPER;
    const int tid = threadIdx.x;
    const int tx = tid & 15, ty = tid >> 4;

    float acc[4][4];
    #pragma unroll
    for (int q = 0; q < 4; ++q)
        #pragma unroll
        for (int p = 0; p < 4; ++p) acc[q][p] = 0.0f;

    for (int kc = 0; kc < KPER; kc += 32) {
        #pragma unroll
        for (int l = tid; l < 2048; l += 256) {
            int ii = l >> 5, kk = l & 31;
            As[kk][ii] = A[(size_t)(i0 + ii) * KTOT + k0 + kc + kk];
            Bs[kk][ii] = B[(size_t)(j0 + ii) * KTOT + k0 + kc + kk];
        }
        __syncthreads();
        #pragma unroll
        for (int kk = 0; kk < 32; ++kk) {
            float a0 = As[kk][ty * 4 + 0], a1 = As[kk][ty * 4 + 1];
            float a2 = As[kk][ty * 4 + 2], a3 = As[kk][ty * 4 + 3];
            float b0 = Bs[kk][tx * 4 + 0], b1 = Bs[kk][tx * 4 + 1];
            float b2 = Bs[kk][tx * 4 + 2], b3 = Bs[kk][tx * 4 + 3];
            acc[0][0] += a0 * b0; acc[0][1] += a0 * b1; acc[0][2] += a0 * b2; acc[0][3] += a0 * b3;
            acc[1][0] += a1 * b0; acc[1][1] += a1 * b1; acc[1][2] += a1 * b2; acc[1][3] += a1 * b3;
            acc[2][0] += a2 * b0; acc[2][1] += a2 * b1; acc[2][2] += a2 * b2; acc[2][3] += a2 * b3;
            acc[3][0] += a3 * b0; acc[3][1] += a3 * b1; acc[3][2] += a3 * b2; acc[3][3] += a3 * b3;
        }
        __syncthreads();
    }

    float* G = g_gram + (size_t)blockIdx.y * 16384;
    #pragma unroll
    for (int q = 0; q < 4; ++q)
        #pragma unroll
        for (int p = 0; p < 4; ++p)
            G[(i0 + ty * 4 + q) * 128 + (j0 + tx * 4 + p)] = acc[q][p];
}

// =====================================================================
// PSD reduce: avg over 256 images per frequency, then per-block partial
// sums of log(avg) and avg.  grid 128 x 128 threads (thread = 1 freq).
// =====================================================================
__global__ __launch_bounds__(128)
void psd_reduce_kernel() {
    const int f = blockIdx.x * 128 + threadIdx.x;
    float s = 0.0f;
    for (int img = 0; img < NIMG; ++img) s += g_psd[(size_t)img * KTOT + f];
    float avg = s * (1.0f / 256.0f);
    float lg = logf(avg);

    __shared__ float redl[4], reda[4];
    float sl = lg, sa = avg;
    #pragma unroll
    for (int o = 16; o > 0; o >>= 1) {
        sl += __shfl_xor_sync(0xFFFFFFFFu, sl, o);
        sa += __shfl_xor_sync(0xFFFFFFFFu, sa, o);
    }
    if ((threadIdx.x & 31) == 0) {
        redl[threadIdx.x >> 5] = sl;
        reda[threadIdx.x >> 5] = sa;
    }
    __syncthreads();
    if (threadIdx.x == 0) {
        g_psd_part[blockIdx.x]       = redl[0] + redl[1] + redl[2] + redl[3];
        g_psd_part[128 + blockIdx.x] = reda[0] + reda[1] + reda[2] + reda[3];
    }
}

// =====================================================================
// Per-row: assemble Dist, row LSE, diag log-prob. grid 128, 128 thr.
// =====================================================================
__global__ __launch_bounds__(128)
void softmax_kernel() {
    const int i = blockIdx.x;
    const int j = threadIdx.x;

    float g = 0.0f;
    #pragma unroll 8
    for (int ks = 0; ks < KSLICES; ++ks) g += g_gram[(size_t)ks * 16384 + i * 128 + j];
    float d2 = g_norm[i] + g_norm[128 + j] - 2.0f * g;
    float dist = sqrtf(fmaxf(d2, 0.0f));

    __shared__ float red[8];
    // row max
    float m = dist;
    #pragma unroll
    for (int o = 16; o > 0; o >>= 1) m = fmaxf(m, __shfl_xor_sync(0xFFFFFFFFu, m, o));
    if ((j & 31) == 0) red[j >> 5] = m;
    __syncthreads();
    float bm = fmaxf(fmaxf(red[0], red[1]), fmaxf(red[2], red[3]));
    // sum exp
    float e = expf(dist - bm);
    #pragma unroll
    for (int o = 16; o > 0; o >>= 1) e += __shfl_xor_sync(0xFFFFFFFFu, e, o);
    if ((j & 31) == 0) red[4 + (j >> 5)] = e;
    __syncthreads();
    float bs = red[4] + red[5] + red[6] + red[7];

    if (j == i) g_rowvals[i] = dist - (bm + logf(bs));
}

// =====================================================================
// Final scalar: ce - REG * r
// =====================================================================
__global__ __launch_bounds__(128)
void final_kernel(float* __restrict__ out) {
    const int t = threadIdx.x;
    float rv = g_rowvals[t];          // 128 diag log-probs
    float p1 = g_psd_part[t];         // 128 partial sum(log avg)
    float p2 = g_psd_part[128 + t];   // 128 partial sum(avg)

    __shared__ float red[12];
    #pragma unroll
    for (int o = 16; o > 0; o >>= 1) {
        rv += __shfl_xor_sync(0xFFFFFFFFu, rv, o);
        p1 += __shfl_xor_sync(0xFFFFFFFFu, p1, o);
        p2 += __shfl_xor_sync(0xFFFFFFFFu, p2, o);
    }
    int w = t >> 5;
    if ((t & 31) == 0) { red[w] = rv; red[4 + w] = p1; red[8 + w] = p2; }
    __syncthreads();
    if (t == 0) {
        float srv = red[0] + red[1] + red[2] + red[3];
        float s1  = red[4] + red[5] + red[6] + red[7];
        float s2  = red[8] + red[9] + red[10] + red[11];
        float ce = -(srv * (1.0f / 128.0f));
        float r  = s1 * (1.0f / 16384.0f) - logf(s2 * (1.0f / 16384.0f));
        out[0] = ce - 0.1f * r;
    }
}

// =====================================================================
extern "C" void kernel_launch(void* const* d_in, const int* in_sizes, int n_in,
                              void* d_out, int out_size) {
    const float* x1 = (const float*)d_in[0];
    const float* x2 = (const float*)d_in[1];
    float* out = (float*)d_out;

    cudaFuncSetAttribute(fft_psd_kernel,
                         cudaFuncAttributeMaxDynamicSharedMemorySize, FFT_SMEM);

    fft_psd_kernel<<<NIMG, 256, FFT_SMEM>>>(x1, x2);
    norm_kernel<<<256, 256>>>(x1, x2);
    gram_kernel<<<dim3(4, 64), 256>>>(x1, x2);
    psd_reduce_kernel<<<128, 128>>>();
    softmax_kernel<<<128, 128>>>();
    final_kernel<<<1, 128>>>(out);
}

// round 4
// speedup vs baseline: 1.4452x; 1.4452x over previous
#include <cuda_runtime.h>
#include <math.h>

#define HW 128
#define NIMG 256            // 128 a-images + 128 b-images
#define KTOT 16384          // HW*HW
#define KSLICES 64          // split-K for gram
#define KPER 256            // K per slice

// ---- scratch (device globals: allocation-free) ----
__device__ float g_psd[NIMG * KTOT];          // per-image |FFT2|^2   (16 MB)
__device__ float g_psd_p1[8 * KTOT];          // stage-1 image-group partials (512 KB)
__device__ float g_gram[KSLICES * 128 * 128]; // split-K gram partials (4 MB)
__device__ float g_norm[256];                 // row squared norms (a then b)
__device__ float g_rowvals[128];              // diag log-prob per row
__device__ float g_psd_part[256];             // [0:128) sum(log avg), [128:256) sum(avg)

// =====================================================================
// complex helpers
// =====================================================================
__device__ __forceinline__ float2 cadd(float2 a, float2 b) { return make_float2(a.x + b.x, a.y + b.y); }
__device__ __forceinline__ float2 csub(float2 a, float2 b) { return make_float2(a.x - b.x, a.y - b.y); }
__device__ __forceinline__ float2 cmul(float2 a, float2 w) {
    return make_float2(a.x * w.x - a.y * w.y, a.x * w.y + a.y * w.x);
}

// =====================================================================
// 2D FFT, radix-2 DIF with 3 stages fused in registers per smem exchange
// (7 stages = 3 + 3 + 1). No bit reversal (PSD stats permutation-invariant).
// One block per image, 1024 threads (thread t: line = t&127, sub = t>>7).
// smem: 128 x pitch-129 float2 (conflict-free in both passes) + 64 twiddles.
// =====================================================================
#define FFT_SMEM ((128 * 129 + 64) * (int)sizeof(float2))

// Level 1: stages h=64,32,16 on points j+16k (k=0..7), j in [0,16)
template<int S>
__device__ __forceinline__ void fft_level1(float2* d, int j, const float2* tw) {
    float2 u[8];
    #pragma unroll
    for (int k = 0; k < 8; ++k) u[k] = d[(j + 16 * k) * S];
    // stage h=64: pairs (k, k+4), twiddle tw[(j+16k)]
    float2 a[8];
    #pragma unroll
    for (int k = 0; k < 4; ++k) {
        a[k]     = cadd(u[k], u[k + 4]);
        a[k + 4] = cmul(csub(u[k], u[k + 4]), tw[j + 16 * k]);
    }
    // stage h=32: pairs (0,2)(1,3)(4,6)(5,7), twiddles tw[2j] / tw[2j+32]
    float2 w0 = tw[2 * j], w1 = tw[2 * j + 32];
    float2 b[8];
    b[0] = cadd(a[0], a[2]); b[2] = cmul(csub(a[0], a[2]), w0);
    b[1] = cadd(a[1], a[3]); b[3] = cmul(csub(a[1], a[3]), w1);
    b[4] = cadd(a[4], a[6]); b[6] = cmul(csub(a[4], a[6]), w0);
    b[5] = cadd(a[5], a[7]); b[7] = cmul(csub(a[5], a[7]), w1);
    // stage h=16: pairs (0,1)(2,3)(4,5)(6,7), twiddle tw[4j]
    float2 w2 = tw[4 * j];
    float2 c[8];
    #pragma unroll
    for (int k = 0; k < 8; k += 2) {
        c[k]     = cadd(b[k], b[k + 1]);
        c[k + 1] = cmul(csub(b[k], b[k + 1]), w2);
    }
    #pragma unroll
    for (int k = 0; k < 8; ++k) d[(j + 16 * k) * S] = c[k];
}

// Level 2: stages h=8,4,2 on points p+2k (k=0..7), p = 16m + j, j in {0,1}
template<int S>
__device__ __forceinline__ void fft_level2(float2* d, int m, int j, const float2* tw) {
    const int p = 16 * m + j;
    float2 u[8];
    #pragma unroll
    for (int k = 0; k < 8; ++k) u[k] = d[(p + 2 * k) * S];
    // stage h=8: pairs (k,k+4), twiddle tw[8j+16k]
    float2 a[8];
    #pragma unroll
    for (int k = 0; k < 4; ++k) {
        a[k]     = cadd(u[k], u[k + 4]);
        a[k + 4] = cmul(csub(u[k], u[k + 4]), tw[8 * j + 16 * k]);
    }
    // stage h=4: pairs (0,2)(1,3)(4,6)(5,7), twiddles tw[16j] / tw[16j+32]
    float2 w0 = tw[16 * j], w1 = tw[16 * j + 32];
    float2 b[8];
    b[0] = cadd(a[0], a[2]); b[2] = cmul(csub(a[0], a[2]), w0);
    b[1] = cadd(a[1], a[3]); b[3] = cmul(csub(a[1], a[3]), w1);
    b[4] = cadd(a[4], a[6]); b[6] = cmul(csub(a[4], a[6]), w0);
    b[5] = cadd(a[5], a[7]); b[7] = cmul(csub(a[5], a[7]), w1);
    // stage h=2: pairs (0,1)(2,3)(4,5)(6,7), twiddle tw[32j]
    float2 w2 = tw[32 * j];
    float2 c[8];
    #pragma unroll
    for (int k = 0; k < 8; k += 2) {
        c[k]     = cadd(b[k], b[k + 1]);
        c[k + 1] = cmul(csub(b[k], b[k + 1]), w2);
    }
    #pragma unroll
    for (int k = 0; k < 8; ++k) d[(p + 2 * k) * S] = c[k];
}

// Level 3: single stage h=1, pairs (2m, 2m+1), twiddle = 1
template<int S>
__device__ __forceinline__ void fft_level3(float2* d, int m) {
    float2 u = d[(2 * m) * S];
    float2 v = d[(2 * m + 1) * S];
    d[(2 * m) * S]     = cadd(u, v);
    d[(2 * m + 1) * S] = csub(u, v);
}

__global__ __launch_bounds__(1024, 1)
void fft_psd_kernel(const float* __restrict__ x1, const float* __restrict__ x2) {
    extern __shared__ float2 sm[];
    float2* data = sm;                 // 128 * 129
    float2* tw   = sm + 128 * 129;     // 64 twiddles

    const int t    = threadIdx.x;      // 1024 threads
    const int line = t & 127;
    const int sub  = t >> 7;           // 0..7
    const int img  = blockIdx.x;
    const float* src = (img < 128) ? (x1 + (size_t)img * KTOT)
                                   : (x2 + (size_t)(img - 128) * KTOT);

    if (t < 64) {
        float s, c;
        sincosf(-6.283185307179586f * (float)t * (1.0f / 128.0f), &s, &c);
        tw[t] = make_float2(c, s);
    }
    #pragma unroll
    for (int idx = t; idx < KTOT; idx += 1024) {
        data[(idx >> 7) * 129 + (idx & 127)] = make_float2(src[idx], 0.0f);
    }
    __syncthreads();

    // ---- pass 1: row FFTs (stride 1, base = line*129) ----
    {
        float2* d = data + line * 129;
        #pragma unroll
        for (int i = 0; i < 2; ++i) fft_level1<1>(d, 2 * sub + i, tw);
        __syncthreads();
        #pragma unroll
        for (int i = 0; i < 2; ++i) {
            int g = 2 * sub + i;
            fft_level2<1>(d, g >> 1, g & 1, tw);
        }
        __syncthreads();
        #pragma unroll
        for (int i = 0; i < 8; ++i) fft_level3<1>(d, 8 * sub + i);
        __syncthreads();
    }
    // ---- pass 2: column FFTs (stride 129, base = line) ----
    {
        float2* d = data + line;
        #pragma unroll
        for (int i = 0; i < 2; ++i) fft_level1<129>(d, 2 * sub + i, tw);
        __syncthreads();
        #pragma unroll
        for (int i = 0; i < 2; ++i) {
            int g = 2 * sub + i;
            fft_level2<129>(d, g >> 1, g & 1, tw);
        }
        __syncthreads();
        #pragma unroll
        for (int i = 0; i < 8; ++i) fft_level3<129>(d, 8 * sub + i);
        __syncthreads();
    }

    float* dst = g_psd + (size_t)img * KTOT;
    #pragma unroll
    for (int idx = t; idx < KTOT; idx += 1024) {
        float2 v = data[(idx >> 7) * 129 + (idx & 127)];
        dst[idx] = v.x * v.x + v.y * v.y;
    }
}

// =====================================================================
// Row squared norms for a (rows 0..127) and b (rows 128..255)
// =====================================================================
__global__ __launch_bounds__(256)
void norm_kernel(const float* __restrict__ x1, const float* __restrict__ x2) {
    const int row = blockIdx.x;
    const float* src = (row < 128) ? (x1 + (size_t)row * KTOT)
                                   : (x2 + (size_t)(row - 128) * KTOT);
    float s = 0.0f;
    for (int k = threadIdx.x; k < KTOT; k += 256) {
        float v = src[k];
        s += v * v;
    }
    __shared__ float red[8];
    #pragma unroll
    for (int o = 16; o > 0; o >>= 1) s += __shfl_xor_sync(0xFFFFFFFFu, s, o);
    if ((threadIdx.x & 31) == 0) red[threadIdx.x >> 5] = s;
    __syncthreads();
    if (threadIdx.x == 0) {
        float tot = 0.0f;
        #pragma unroll
        for (int w = 0; w < 8; ++w) tot += red[w];
        g_norm[row] = tot;
    }
}

// =====================================================================
// Split-K Gram: G_part[ks][i][j] = sum_{k in slice ks} a[i][k]*b[j][k]
// =====================================================================
__global__ __launch_bounds__(256)
void gram_kernel(const float* __restrict__ A, const float* __restrict__ B) {
    __shared__ float As[32][65];
    __shared__ float Bs[32][65];
    const int i0 = (blockIdx.x & 1) * 64;
    const int j0 = (blockIdx.x >> 1) * 64;
    const int k0 = blockIdx.y * KPER;
    const int tid = threadIdx.x;
    const int tx = tid & 15, ty = tid >> 4;

    float acc[4][4];
    #pragma unroll
    for (int q = 0; q < 4; ++q)
        #pragma unroll
        for (int p = 0; p < 4; ++p) acc[q][p] = 0.0f;

    for (int kc = 0; kc < KPER; kc += 32) {
        #pragma unroll
        for (int l = tid; l < 2048; l += 256) {
            int ii = l >> 5, kk = l & 31;
            As[kk][ii] = A[(size_t)(i0 + ii) * KTOT + k0 + kc + kk];
            Bs[kk][ii] = B[(size_t)(j0 + ii) * KTOT + k0 + kc + kk];
        }
        __syncthreads();
        #pragma unroll
        for (int kk = 0; kk < 32; ++kk) {
            float a0 = As[kk][ty * 4 + 0], a1 = As[kk][ty * 4 + 1];
            float a2 = As[kk][ty * 4 + 2], a3 = As[kk][ty * 4 + 3];
            float b0 = Bs[kk][tx * 4 + 0], b1 = Bs[kk][tx * 4 + 1];
            float b2 = Bs[kk][tx * 4 + 2], b3 = Bs[kk][tx * 4 + 3];
            acc[0][0] += a0 * b0; acc[0][1] += a0 * b1; acc[0][2] += a0 * b2; acc[0][3] += a0 * b3;
            acc[1][0] += a1 * b0; acc[1][1] += a1 * b1; acc[1][2] += a1 * b2; acc[1][3] += a1 * b3;
            acc[2][0] += a2 * b0; acc[2][1] += a2 * b1; acc[2][2] += a2 * b2; acc[2][3] += a2 * b3;
            acc[3][0] += a3 * b0; acc[3][1] += a3 * b1; acc[3][2] += a3 * b2; acc[3][3] += a3 * b3;
        }
        __syncthreads();
    }

    float* G = g_gram + (size_t)blockIdx.y * 16384;
    #pragma unroll
    for (int q = 0; q < 4; ++q)
        #pragma unroll
        for (int p = 0; p < 4; ++p)
            G[(i0 + ty * 4 + q) * 128 + (j0 + tx * 4 + p)] = acc[q][p];
}

// =====================================================================
// PSD reduce stage 1: sum 32 images per (image-group, freq).
// grid (64, 8), 256 thr. Fully coalesced; 16 MB read at high occupancy.
// =====================================================================
__global__ __launch_bounds__(256)
void psd_stage1_kernel() {
    const int f = blockIdx.x * 256 + threadIdx.x;
    const int base = blockIdx.y * 32;
    float s = 0.0f;
    #pragma unroll 8
    for (int im = 0; im < 32; ++im) s += g_psd[(size_t)(base + im) * KTOT + f];
    g_psd_p1[(size_t)blockIdx.y * KTOT + f] = s;
}

// =====================================================================
// PSD reduce stage 2: combine 8 partials, log, block partial sums.
// grid 128 x 128 threads.
// =====================================================================
__global__ __launch_bounds__(128)
void psd_stage2_kernel() {
    const int f = blockIdx.x * 128 + threadIdx.x;
    float s = 0.0f;
    #pragma unroll
    for (int ig = 0; ig < 8; ++ig) s += g_psd_p1[(size_t)ig * KTOT + f];
    float avg = s * (1.0f / 256.0f);
    float lg = logf(avg);

    __shared__ float redl[4], reda[4];
    float sl = lg, sa = avg;
    #pragma unroll
    for (int o = 16; o > 0; o >>= 1) {
        sl += __shfl_xor_sync(0xFFFFFFFFu, sl, o);
        sa += __shfl_xor_sync(0xFFFFFFFFu, sa, o);
    }
    if ((threadIdx.x & 31) == 0) {
        redl[threadIdx.x >> 5] = sl;
        reda[threadIdx.x >> 5] = sa;
    }
    __syncthreads();
    if (threadIdx.x == 0) {
        g_psd_part[blockIdx.x]       = redl[0] + redl[1] + redl[2] + redl[3];
        g_psd_part[128 + blockIdx.x] = reda[0] + reda[1] + reda[2] + reda[3];
    }
}

// =====================================================================
// Per-row: assemble Dist, row LSE, diag log-prob. grid 128, 128 thr.
// =====================================================================
__global__ __launch_bounds__(128)
void softmax_kernel() {
    const int i = blockIdx.x;
    const int j = threadIdx.x;

    float g = 0.0f;
    #pragma unroll 8
    for (int ks = 0; ks < KSLICES; ++ks) g += g_gram[(size_t)ks * 16384 + i * 128 + j];
    float d2 = g_norm[i] + g_norm[128 + j] - 2.0f * g;
    float dist = sqrtf(fmaxf(d2, 0.0f));

    __shared__ float red[8];
    float m = dist;
    #pragma unroll
    for (int o = 16; o > 0; o >>= 1) m = fmaxf(m, __shfl_xor_sync(0xFFFFFFFFu, m, o));
    if ((j & 31) == 0) red[j >> 5] = m;
    __syncthreads();
    float bm = fmaxf(fmaxf(red[0], red[1]), fmaxf(red[2], red[3]));
    float e = expf(dist - bm);
    #pragma unroll
    for (int o = 16; o > 0; o >>= 1) e += __shfl_xor_sync(0xFFFFFFFFu, e, o);
    if ((j & 31) == 0) red[4 + (j >> 5)] = e;
    __syncthreads();
    float bs = red[4] + red[5] + red[6] + red[7];

    if (j == i) g_rowvals[i] = dist - (bm + logf(bs));
}

// =====================================================================
// Final scalar: ce - REG * r
// =====================================================================
__global__ __launch_bounds__(128)
void final_kernel(float* __restrict__ out) {
    const int t = threadIdx.x;
    float rv = g_rowvals[t];
    float p1 = g_psd_part[t];
    float p2 = g_psd_part[128 + t];

    __shared__ float red[12];
    #pragma unroll
    for (int o = 16; o > 0; o >>= 1) {
        rv += __shfl_xor_sync(0xFFFFFFFFu, rv, o);
        p1 += __shfl_xor_sync(0xFFFFFFFFu, p1, o);
        p2 += __shfl_xor_sync(0xFFFFFFFFu, p2, o);
    }
    int w = t >> 5;
    if ((t & 31) == 0) { red[w] = rv; red[4 + w] = p1; red[8 + w] = p2; }
    __syncthreads();
    if (t == 0) {
        float srv = red[0] + red[1] + red[2] + red[3];
        float s1  = red[4] + red[5] + red[6] + red[7];
        float s2  = red[8] + red[9] + red[10] + red[11];
        float ce = -(srv * (1.0f / 128.0f));
        float r  = s1 * (1.0f / 16384.0f) - logf(s2 * (1.0f / 16384.0f));
        out[0] = ce - 0.1f * r;
    }
}

// =====================================================================
extern "C" void kernel_launch(void* const* d_in, const int* in_sizes, int n_in,
                              void* d_out, int out_size) {
    const float* x1 = (const float*)d_in[0];
    const float* x2 = (const float*)d_in[1];
    float* out = (float*)d_out;

    cudaFuncSetAttribute(fft_psd_kernel,
                         cudaFuncAttributeMaxDynamicSharedMemorySize, FFT_SMEM);

    fft_psd_kernel<<<NIMG, 1024, FFT_SMEM>>>(x1, x2);
    norm_kernel<<<256, 256>>>(x1, x2);
    gram_kernel<<<dim3(4, 64), 256>>>(x1, x2);
    psd_stage1_kernel<<<dim3(64, 8), 256>>>();
    psd_stage2_kernel<<<128, 128>>>();
    softmax_kernel<<<128, 128>>>();
    final_kernel<<<1, 128>>>(out);
}

// round 5
// speedup vs baseline: 1.8102x; 1.2525x over previous
#include <cuda_runtime.h>
#include <math.h>

#define HW 128
#define NPAIR 128           // 128 packed complex images (a_p + i*b_p)
#define KTOT 16384          // HW*HW
#define KSLICES 64          // split-K for gram
#define KPER 256            // K per slice

// ---- scratch (device globals: allocation-free) ----
__device__ float g_psd[NPAIR * KTOT];         // per-pair summed |F_a|^2+|F_b|^2  (8 MB)
__device__ float g_psd_p1[8 * KTOT];          // stage-1 pair-group partials (512 KB)
__device__ float g_gram[KSLICES * 128 * 128]; // split-K gram partials (4 MB)
__device__ float g_norm[256];                 // row squared norms (a then b)
__device__ float g_rowvals[128];              // diag log-prob per row
__device__ float g_psd_part[256];             // [0:128) sum(log avg), [128:256) sum(avg)

// =====================================================================
// complex helpers
// =====================================================================
__device__ __forceinline__ float2 cadd(float2 a, float2 b) { return make_float2(a.x + b.x, a.y + b.y); }
__device__ __forceinline__ float2 csub(float2 a, float2 b) { return make_float2(a.x - b.x, a.y - b.y); }
__device__ __forceinline__ float2 cmul(float2 a, float2 w) {
    return make_float2(a.x * w.x - a.y * w.y, a.x * w.y + a.y * w.x);
}

// =====================================================================
// 2D FFT of packed complex image z = a + i*b (radix-2 DIF, 3 stages fused
// per smem exchange, no bit reversal). PSD recovered via conjugate
// symmetry: |F_a|^2+|F_b|^2 at freq (u,v) = (|Z(u,v)|^2+|Z(-u,-v)|^2)/2.
// Output slot s holds freq bitrev7(s); partner slot via msk[] table.
// Also computes ||a||^2, ||b||^2 during the load (free norm kernel).
// One block per pair, 1024 threads.  128 blocks = one wave on 148 SMs.
// =====================================================================
#define FFT_SMEM ((128 * 129 + 64) * (int)sizeof(float2))

// Level 1: stages h=64,32,16 on points j+16k (k=0..7), j in [0,16)
template<int S>
__device__ __forceinline__ void fft_level1(float2* d, int j, const float2* tw) {
    float2 u[8];
    #pragma unroll
    for (int k = 0; k < 8; ++k) u[k] = d[(j + 16 * k) * S];
    float2 a[8];
    #pragma unroll
    for (int k = 0; k < 4; ++k) {
        a[k]     = cadd(u[k], u[k + 4]);
        a[k + 4] = cmul(csub(u[k], u[k + 4]), tw[j + 16 * k]);
    }
    float2 w0 = tw[2 * j], w1 = tw[2 * j + 32];
    float2 b[8];
    b[0] = cadd(a[0], a[2]); b[2] = cmul(csub(a[0], a[2]), w0);
    b[1] = cadd(a[1], a[3]); b[3] = cmul(csub(a[1], a[3]), w1);
    b[4] = cadd(a[4], a[6]); b[6] = cmul(csub(a[4], a[6]), w0);
    b[5] = cadd(a[5], a[7]); b[7] = cmul(csub(a[5], a[7]), w1);
    float2 w2 = tw[4 * j];
    float2 c[8];
    #pragma unroll
    for (int k = 0; k < 8; k += 2) {
        c[k]     = cadd(b[k], b[k + 1]);
        c[k + 1] = cmul(csub(b[k], b[k + 1]), w2);
    }
    #pragma unroll
    for (int k = 0; k < 8; ++k) d[(j + 16 * k) * S] = c[k];
}

// Level 2: stages h=8,4,2 on points p+2k (k=0..7), p = 16m + j, j in {0,1}
template<int S>
__device__ __forceinline__ void fft_level2(float2* d, int m, int j, const float2* tw) {
    const int p = 16 * m + j;
    float2 u[8];
    #pragma unroll
    for (int k = 0; k < 8; ++k) u[k] = d[(p + 2 * k) * S];
    float2 a[8];
    #pragma unroll
    for (int k = 0; k < 4; ++k) {
        a[k]     = cadd(u[k], u[k + 4]);
        a[k + 4] = cmul(csub(u[k], u[k + 4]), tw[8 * j + 16 * k]);
    }
    float2 w0 = tw[16 * j], w1 = tw[16 * j + 32];
    float2 b[8];
    b[0] = cadd(a[0], a[2]); b[2] = cmul(csub(a[0], a[2]), w0);
    b[1] = cadd(a[1], a[3]); b[3] = cmul(csub(a[1], a[3]), w1);
    b[4] = cadd(a[4], a[6]); b[6] = cmul(csub(a[4], a[6]), w0);
    b[5] = cadd(a[5], a[7]); b[7] = cmul(csub(a[5], a[7]), w1);
    float2 w2 = tw[32 * j];
    float2 c[8];
    #pragma unroll
    for (int k = 0; k < 8; k += 2) {
        c[k]     = cadd(b[k], b[k + 1]);
        c[k + 1] = cmul(csub(b[k], b[k + 1]), w2);
    }
    #pragma unroll
    for (int k = 0; k < 8; ++k) d[(p + 2 * k) * S] = c[k];
}

// Level 3: single stage h=1, pairs (2m, 2m+1), twiddle = 1
template<int S>
__device__ __forceinline__ void fft_level3(float2* d, int m) {
    float2 u = d[(2 * m) * S];
    float2 v = d[(2 * m + 1) * S];
    d[(2 * m) * S]     = cadd(u, v);
    d[(2 * m + 1) * S] = csub(u, v);
}

__global__ __launch_bounds__(1024, 1)
void fft_psd_kernel(const float* __restrict__ x1, const float* __restrict__ x2) {
    extern __shared__ float2 sm[];
    float2* data = sm;                 // 128 * 129
    float2* tw   = sm + 128 * 129;     // 64 twiddles
    __shared__ int   msk[128];         // slot -> partner slot (freq negation)
    __shared__ float redn[64];         // norm reduction scratch

    const int t    = threadIdx.x;      // 1024 threads
    const int line = t & 127;
    const int sub  = t >> 7;           // 0..7
    const int img  = blockIdx.x;       // pair index 0..127
    const float* sa = x1 + (size_t)img * KTOT;
    const float* sb = x2 + (size_t)img * KTOT;

    if (t < 64) {
        float s, c;
        sincosf(-6.283185307179586f * (float)t * (1.0f / 128.0f), &s, &c);
        tw[t] = make_float2(c, s);
    }
    if (t < 128) {
        unsigned r = __brev((unsigned)t) >> 25;       // bitrev7(s)
        unsigned n = (128u - r) & 127u;               // negate frequency
        msk[t] = (int)(__brev(n) >> 25);              // back to slot space
    }

    float na = 0.0f, nb = 0.0f;
    #pragma unroll
    for (int idx = t; idx < KTOT; idx += 1024) {
        float va = sa[idx];
        float vb = sb[idx];
        na += va * va;
        nb += vb * vb;
        data[(idx >> 7) * 129 + (idx & 127)] = make_float2(va, vb);
    }
    // block-reduce norms (deterministic fixed order)
    #pragma unroll
    for (int o = 16; o > 0; o >>= 1) {
        na += __shfl_xor_sync(0xFFFFFFFFu, na, o);
        nb += __shfl_xor_sync(0xFFFFFFFFu, nb, o);
    }
    if ((t & 31) == 0) { redn[t >> 5] = na; redn[32 + (t >> 5)] = nb; }
    __syncthreads();   // covers data, tw, msk, redn
    if (t == 0) {
        float ta = 0.0f, tb = 0.0f;
        #pragma unroll
        for (int w = 0; w < 32; ++w) { ta += redn[w]; tb += redn[32 + w]; }
        g_norm[img] = ta;
        g_norm[128 + img] = tb;
    }

    // ---- pass 1: row FFTs (stride 1) ----
    {
        float2* d = data + line * 129;
        #pragma unroll
        for (int i = 0; i < 2; ++i) fft_level1<1>(d, 2 * sub + i, tw);
        __syncthreads();
        #pragma unroll
        for (int i = 0; i < 2; ++i) {
            int g = 2 * sub + i;
            fft_level2<1>(d, g >> 1, g & 1, tw);
        }
        __syncthreads();
        #pragma unroll
        for (int i = 0; i < 8; ++i) fft_level3<1>(d, 8 * sub + i);
        __syncthreads();
    }
    // ---- pass 2: column FFTs (stride 129) ----
    {
        float2* d = data + line;
        #pragma unroll
        for (int i = 0; i < 2; ++i) fft_level1<129>(d, 2 * sub + i, tw);
        __syncthreads();
        #pragma unroll
        for (int i = 0; i < 2; ++i) {
            int g = 2 * sub + i;
            fft_level2<129>(d, g >> 1, g & 1, tw);
        }
        __syncthreads();
        #pragma unroll
        for (int i = 0; i < 8; ++i) fft_level3<129>(d, 8 * sub + i);
        __syncthreads();
    }

    // |F_a|^2 + |F_b|^2 via conjugate-symmetry unpacking
    float* dst = g_psd + (size_t)img * KTOT;
    #pragma unroll
    for (int idx = t; idx < KTOT; idx += 1024) {
        int i = idx >> 7, j = idx & 127;
        float2 z1 = data[i * 129 + j];
        float2 z2 = data[msk[i] * 129 + msk[j]];
        dst[idx] = 0.5f * (z1.x * z1.x + z1.y * z1.y + z2.x * z2.x + z2.y * z2.y);
    }
}

// =====================================================================
// Split-K Gram: G_part[ks][i][j] = sum_{k in slice ks} a[i][k]*b[j][k]
// =====================================================================
__global__ __launch_bounds__(256)
void gram_kernel(const float* __restrict__ A, const float* __restrict__ B) {
    __shared__ float As[32][65];
    __shared__ float Bs[32][65];
    const int i0 = (blockIdx.x & 1) * 64;
    const int j0 = (blockIdx.x >> 1) * 64;
    const int k0 = blockIdx.y * KPER;
    const int tid = threadIdx.x;
    const int tx = tid & 15, ty = tid >> 4;

    float acc[4][4];
    #pragma unroll
    for (int q = 0; q < 4; ++q)
        #pragma unroll
        for (int p = 0; p < 4; ++p) acc[q][p] = 0.0f;

    for (int kc = 0; kc < KPER; kc += 32) {
        #pragma unroll
        for (int l = tid; l < 2048; l += 256) {
            int ii = l >> 5, kk = l & 31;
            As[kk][ii] = A[(size_t)(i0 + ii) * KTOT + k0 + kc + kk];
            Bs[kk][ii] = B[(size_t)(j0 + ii) * KTOT + k0 + kc + kk];
        }
        __syncthreads();
        #pragma unroll
        for (int kk = 0; kk < 32; ++kk) {
            float a0 = As[kk][ty * 4 + 0], a1 = As[kk][ty * 4 + 1];
            float a2 = As[kk][ty * 4 + 2], a3 = As[kk][ty * 4 + 3];
            float b0 = Bs[kk][tx * 4 + 0], b1 = Bs[kk][tx * 4 + 1];
            float b2 = Bs[kk][tx * 4 + 2], b3 = Bs[kk][tx * 4 + 3];
            acc[0][0] += a0 * b0; acc[0][1] += a0 * b1; acc[0][2] += a0 * b2; acc[0][3] += a0 * b3;
            acc[1][0] += a1 * b0; acc[1][1] += a1 * b1; acc[1][2] += a1 * b2; acc[1][3] += a1 * b3;
            acc[2][0] += a2 * b0; acc[2][1] += a2 * b1; acc[2][2] += a2 * b2; acc[2][3] += a2 * b3;
            acc[3][0] += a3 * b0; acc[3][1] += a3 * b1; acc[3][2] += a3 * b2; acc[3][3] += a3 * b3;
        }
        __syncthreads();
    }

    float* G = g_gram + (size_t)blockIdx.y * 16384;
    #pragma unroll
    for (int q = 0; q < 4; ++q)
        #pragma unroll
        for (int p = 0; p < 4; ++p)
            G[(i0 + ty * 4 + q) * 128 + (j0 + tx * 4 + p)] = acc[q][p];
}

// =====================================================================
// PSD reduce stage 1: sum 16 pairs per (group, freq), float4-vectorized.
// grid (16, 8), 256 thr: thread = one float4 column, 16 loads in flight.
// =====================================================================
__global__ __launch_bounds__(256)
void psd_stage1_kernel() {
    const int f4 = blockIdx.x * 256 + threadIdx.x;   // 0..4095
    const int base = blockIdx.y * 16;
    float4 acc = make_float4(0.f, 0.f, 0.f, 0.f);
    #pragma unroll
    for (int im = 0; im < 16; ++im) {
        const float4 v = ((const float4*)(g_psd + (size_t)(base + im) * KTOT))[f4];
        acc.x += v.x; acc.y += v.y; acc.z += v.z; acc.w += v.w;
    }
    ((float4*)(g_psd_p1 + (size_t)blockIdx.y * KTOT))[f4] = acc;
}

// =====================================================================
// PSD reduce stage 2: combine 8 partials, log, block partial sums.
// =====================================================================
__global__ __launch_bounds__(128)
void psd_stage2_kernel() {
    const int f = blockIdx.x * 128 + threadIdx.x;
    float s = 0.0f;
    #pragma unroll
    for (int ig = 0; ig < 8; ++ig) s += g_psd_p1[(size_t)ig * KTOT + f];
    float avg = s * (1.0f / 256.0f);
    float lg = logf(avg);

    __shared__ float redl[4], reda[4];
    float sl = lg, sa = avg;
    #pragma unroll
    for (int o = 16; o > 0; o >>= 1) {
        sl += __shfl_xor_sync(0xFFFFFFFFu, sl, o);
        sa += __shfl_xor_sync(0xFFFFFFFFu, sa, o);
    }
    if ((threadIdx.x & 31) == 0) {
        redl[threadIdx.x >> 5] = sl;
        reda[threadIdx.x >> 5] = sa;
    }
    __syncthreads();
    if (threadIdx.x == 0) {
        g_psd_part[blockIdx.x]       = redl[0] + redl[1] + redl[2] + redl[3];
        g_psd_part[128 + blockIdx.x] = reda[0] + reda[1] + reda[2] + reda[3];
    }
}

// =====================================================================
// Per-row: assemble Dist, row LSE, diag log-prob. grid 128, 128 thr.
// =====================================================================
__global__ __launch_bounds__(128)
void softmax_kernel() {
    const int i = blockIdx.x;
    const int j = threadIdx.x;

    float g = 0.0f;
    #pragma unroll 8
    for (int ks = 0; ks < KSLICES; ++ks) g += g_gram[(size_t)ks * 16384 + i * 128 + j];
    float d2 = g_norm[i] + g_norm[128 + j] - 2.0f * g;
    float dist = sqrtf(fmaxf(d2, 0.0f));

    __shared__ float red[8];
    float m = dist;
    #pragma unroll
    for (int o = 16; o > 0; o >>= 1) m = fmaxf(m, __shfl_xor_sync(0xFFFFFFFFu, m, o));
    if ((j & 31) == 0) red[j >> 5] = m;
    __syncthreads();
    float bm = fmaxf(fmaxf(red[0], red[1]), fmaxf(red[2], red[3]));
    float e = expf(dist - bm);
    #pragma unroll
    for (int o = 16; o > 0; o >>= 1) e += __shfl_xor_sync(0xFFFFFFFFu, e, o);
    if ((j & 31) == 0) red[4 + (j >> 5)] = e;
    __syncthreads();
    float bs = red[4] + red[5] + red[6] + red[7];

    if (j == i) g_rowvals[i] = dist - (bm + logf(bs));
}

// =====================================================================
// Final scalar: ce - REG * r
// =====================================================================
__global__ __launch_bounds__(128)
void final_kernel(float* __restrict__ out) {
    const int t = threadIdx.x;
    float rv = g_rowvals[t];
    float p1 = g_psd_part[t];
    float p2 = g_psd_part[128 + t];

    __shared__ float red[12];
    #pragma unroll
    for (int o = 16; o > 0; o >>= 1) {
        rv += __shfl_xor_sync(0xFFFFFFFFu, rv, o);
        p1 += __shfl_xor_sync(0xFFFFFFFFu, p1, o);
        p2 += __shfl_xor_sync(0xFFFFFFFFu, p2, o);
    }
    int w = t >> 5;
    if ((t & 31) == 0) { red[w] = rv; red[4 + w] = p1; red[8 + w] = p2; }
    __syncthreads();
    if (t == 0) {
        float srv = red[0] + red[1] + red[2] + red[3];
        float s1  = red[4] + red[5] + red[6] + red[7];
        float s2  = red[8] + red[9] + red[10] + red[11];
        float ce = -(srv * (1.0f / 128.0f));
        float r  = s1 * (1.0f / 16384.0f) - logf(s2 * (1.0f / 16384.0f));
        out[0] = ce - 0.1f * r;
    }
}

// =====================================================================
extern "C" void kernel_launch(void* const* d_in, const int* in_sizes, int n_in,
                              void* d_out, int out_size) {
    const float* x1 = (const float*)d_in[0];
    const float* x2 = (const float*)d_in[1];
    float* out = (float*)d_out;

    cudaFuncSetAttribute(fft_psd_kernel,
                         cudaFuncAttributeMaxDynamicSharedMemorySize, FFT_SMEM);

    fft_psd_kernel<<<NPAIR, 1024, FFT_SMEM>>>(x1, x2);
    gram_kernel<<<dim3(4, 64), 256>>>(x1, x2);
    psd_stage1_kernel<<<dim3(16, 8), 256>>>();
    psd_stage2_kernel<<<128, 128>>>();
    softmax_kernel<<<128, 128>>>();
    final_kernel<<<1, 128>>>(out);
}

// round 7
// speedup vs baseline: 1.9209x; 1.0612x over previous
#include <cuda_runtime.h>
#include <math.h>
#include <stdint.h>
#include <mma.h>

using namespace nvcuda;

#define HW 128
#define NPAIR 128           // 128 packed complex images (a + i*b)
#define KTOT 16384          // HW*HW
#define GSLICES 128         // split-K slices for gram
#define GKC 128             // K per slice (per CTA)
#define LDS 36              // smem row stride (32 + 4 pad), floats

// ---- scratch (device globals: allocation-free) ----
__device__ float g_psd[NPAIR * KTOT];            // per-pair |F_a|^2+|F_b|^2 (8 MB)
__device__ float g_gram[GSLICES * 128 * 128];    // split-K gram partials (8 MB)
__device__ float g_norm[256];                    // row squared norms (a then b)
__device__ float g_rowvals[128];                 // diag log-prob per row
__device__ float g_psd_part[256];                // [0:64) sum(log avg), [128:192) sum(avg)

// =====================================================================
// complex helpers
// =====================================================================
__device__ __forceinline__ float2 cadd(float2 a, float2 b) { return make_float2(a.x + b.x, a.y + b.y); }
__device__ __forceinline__ float2 csub(float2 a, float2 b) { return make_float2(a.x - b.x, a.y - b.y); }
__device__ __forceinline__ float2 cmul(float2 a, float2 w) {
    return make_float2(a.x * w.x - a.y * w.y, a.x * w.y + a.y * w.x);
}

// =====================================================================
// 2D FFT of packed z = a + i*b (radix-2 DIF, 3 stages fused per exchange,
// no bit reversal). PSD via conjugate symmetry. Norms fused into load.
// One block per pair, 1024 threads.
// =====================================================================
#define FFT_SMEM ((128 * 129 + 64) * (int)sizeof(float2))

template<int S>
__device__ __forceinline__ void fft_level1(float2* d, int j, const float2* tw) {
    float2 u[8];
    #pragma unroll
    for (int k = 0; k < 8; ++k) u[k] = d[(j + 16 * k) * S];
    float2 a[8];
    #pragma unroll
    for (int k = 0; k < 4; ++k) {
        a[k]     = cadd(u[k], u[k + 4]);
        a[k + 4] = cmul(csub(u[k], u[k + 4]), tw[j + 16 * k]);
    }
    float2 w0 = tw[2 * j], w1 = tw[2 * j + 32];
    float2 b[8];
    b[0] = cadd(a[0], a[2]); b[2] = cmul(csub(a[0], a[2]), w0);
    b[1] = cadd(a[1], a[3]); b[3] = cmul(csub(a[1], a[3]), w1);
    b[4] = cadd(a[4], a[6]); b[6] = cmul(csub(a[4], a[6]), w0);
    b[5] = cadd(a[5], a[7]); b[7] = cmul(csub(a[5], a[7]), w1);
    float2 w2 = tw[4 * j];
    float2 c[8];
    #pragma unroll
    for (int k = 0; k < 8; k += 2) {
        c[k]     = cadd(b[k], b[k + 1]);
        c[k + 1] = cmul(csub(b[k], b[k + 1]), w2);
    }
    #pragma unroll
    for (int k = 0; k < 8; ++k) d[(j + 16 * k) * S] = c[k];
}

template<int S>
__device__ __forceinline__ void fft_level2(float2* d, int m, int j, const float2* tw) {
    const int p = 16 * m + j;
    float2 u[8];
    #pragma unroll
    for (int k = 0; k < 8; ++k) u[k] = d[(p + 2 * k) * S];
    float2 a[8];
    #pragma unroll
    for (int k = 0; k < 4; ++k) {
        a[k]     = cadd(u[k], u[k + 4]);
        a[k + 4] = cmul(csub(u[k], u[k + 4]), tw[8 * j + 16 * k]);
    }
    float2 w0 = tw[16 * j], w1 = tw[16 * j + 32];
    float2 b[8];
    b[0] = cadd(a[0], a[2]); b[2] = cmul(csub(a[0], a[2]), w0);
    b[1] = cadd(a[1], a[3]); b[3] = cmul(csub(a[1], a[3]), w1);
    b[4] = cadd(a[4], a[6]); b[6] = cmul(csub(a[4], a[6]), w0);
    b[5] = cadd(a[5], a[7]); b[7] = cmul(csub(a[5], a[7]), w1);
    float2 w2 = tw[32 * j];
    float2 c[8];
    #pragma unroll
    for (int k = 0; k < 8; k += 2) {
        c[k]     = cadd(b[k], b[k + 1]);
        c[k + 1] = cmul(csub(b[k], b[k + 1]), w2);
    }
    #pragma unroll
    for (int k = 0; k < 8; ++k) d[(p + 2 * k) * S] = c[k];
}

template<int S>
__device__ __forceinline__ void fft_level3(float2* d, int m) {
    float2 u = d[(2 * m) * S];
    float2 v = d[(2 * m + 1) * S];
    d[(2 * m) * S]     = cadd(u, v);
    d[(2 * m + 1) * S] = csub(u, v);
}

__global__ __launch_bounds__(1024, 1)
void fft_psd_kernel(const float* __restrict__ x1, const float* __restrict__ x2) {
    extern __shared__ float2 sm[];
    float2* data = sm;                 // 128 * 129
    float2* tw   = sm + 128 * 129;     // 64 twiddles
    __shared__ int   msk[128];
    __shared__ float redn[64];

    const int t    = threadIdx.x;
    const int line = t & 127;
    const int sub  = t >> 7;
    const int img  = blockIdx.x;
    const float* sa = x1 + (size_t)img * KTOT;
    const float* sb = x2 + (size_t)img * KTOT;

    if (t < 64) {
        float s, c;
        sincosf(-6.283185307179586f * (float)t * (1.0f / 128.0f), &s, &c);
        tw[t] = make_float2(c, s);
    }
    if (t < 128) {
        unsigned r = __brev((unsigned)t) >> 25;
        unsigned n = (128u - r) & 127u;
        msk[t] = (int)(__brev(n) >> 25);
    }

    float na = 0.0f, nb = 0.0f;
    #pragma unroll
    for (int idx = t; idx < KTOT; idx += 1024) {
        float va = sa[idx];
        float vb = sb[idx];
        na += va * va;
        nb += vb * vb;
        data[(idx >> 7) * 129 + (idx & 127)] = make_float2(va, vb);
    }
    #pragma unroll
    for (int o = 16; o > 0; o >>= 1) {
        na += __shfl_xor_sync(0xFFFFFFFFu, na, o);
        nb += __shfl_xor_sync(0xFFFFFFFFu, nb, o);
    }
    if ((t & 31) == 0) { redn[t >> 5] = na; redn[32 + (t >> 5)] = nb; }
    __syncthreads();
    if (t == 0) {
        float ta = 0.0f, tb = 0.0f;
        #pragma unroll
        for (int w = 0; w < 32; ++w) { ta += redn[w]; tb += redn[32 + w]; }
        g_norm[img] = ta;
        g_norm[128 + img] = tb;
    }

    {   // rows
        float2* d = data + line * 129;
        #pragma unroll
        for (int i = 0; i < 2; ++i) fft_level1<1>(d, 2 * sub + i, tw);
        __syncthreads();
        #pragma unroll
        for (int i = 0; i < 2; ++i) { int g = 2 * sub + i; fft_level2<1>(d, g >> 1, g & 1, tw); }
        __syncthreads();
        #pragma unroll
        for (int i = 0; i < 8; ++i) fft_level3<1>(d, 8 * sub + i);
        __syncthreads();
    }
    {   // cols
        float2* d = data + line;
        #pragma unroll
        for (int i = 0; i < 2; ++i) fft_level1<129>(d, 2 * sub + i, tw);
        __syncthreads();
        #pragma unroll
        for (int i = 0; i < 2; ++i) { int g = 2 * sub + i; fft_level2<129>(d, g >> 1, g & 1, tw); }
        __syncthreads();
        #pragma unroll
        for (int i = 0; i < 8; ++i) fft_level3<129>(d, 8 * sub + i);
        __syncthreads();
    }

    float* dst = g_psd + (size_t)img * KTOT;
    #pragma unroll
    for (int idx = t; idx < KTOT; idx += 1024) {
        int i = idx >> 7, j = idx & 127;
        float2 z1 = data[i * 129 + j];
        float2 z2 = data[msk[i] * 129 + msk[j]];
        dst[idx] = 0.5f * (z1.x * z1.x + z1.y * z1.y + z2.x * z2.x + z2.y * z2.y);
    }
}

// =====================================================================
// Gram via warp-level wmma tf32 (m16n16k8) — compute_103-safe tensor path.
// G = A * B^T: matrix_a row-major from A, matrix_b col-major from B
// (col-major k x n view of row-major B[n][k] is exactly B^T).
// One CTA per K-slice of 128; 8 warps in 4x2 grid, each 32x64 of output.
// K staged in chunks of 32 through padded smem.
// =====================================================================
typedef wmma::fragment<wmma::matrix_a, 16, 16, 8, wmma::precision::tf32, wmma::row_major> AFrag;
typedef wmma::fragment<wmma::matrix_b, 16, 16, 8, wmma::precision::tf32, wmma::col_major> BFrag;
typedef wmma::fragment<wmma::accumulator, 16, 16, 8, float> CFrag;

__global__ __launch_bounds__(256)
void gram_wmma_kernel(const float* __restrict__ A, const float* __restrict__ B) {
    __shared__ float As[128 * LDS];
    __shared__ float Bs[128 * LDS];

    const int tid = threadIdx.x;
    const int wid = tid >> 5;
    const int wr  = wid >> 1;          // 0..3 -> rows 32*wr
    const int wc  = wid & 1;           // 0..1 -> cols 64*wc
    const int k0  = blockIdx.x * GKC;

    CFrag acc[2][4];
    #pragma unroll
    for (int m = 0; m < 2; ++m)
        #pragma unroll
        for (int n = 0; n < 4; ++n) wmma::fill_fragment(acc[m][n], 0.0f);

    for (int kc = 0; kc < GKC; kc += 32) {
        #pragma unroll
        for (int idx = tid; idx < 1024; idx += 256) {
            int row = idx >> 3;        // 0..127
            int q   = idx & 7;         // float4 column
            float4 va = *(const float4*)(A + (size_t)row * KTOT + k0 + kc + q * 4);
            float4 vb = *(const float4*)(B + (size_t)row * KTOT + k0 + kc + q * 4);
            *(float4*)(As + row * LDS + q * 4) = va;
            *(float4*)(Bs + row * LDS + q * 4) = vb;
        }
        __syncthreads();
        #pragma unroll
        for (int kk = 0; kk < 32; kk += 8) {
            AFrag fa[2];
            BFrag fb[4];
            #pragma unroll
            for (int m = 0; m < 2; ++m) {
                wmma::load_matrix_sync(fa[m], As + (wr * 32 + m * 16) * LDS + kk, LDS);
                #pragma unroll
                for (int e = 0; e < fa[m].num_elements; ++e)
                    fa[m].x[e] = wmma::__float_to_tf32(fa[m].x[e]);
            }
            #pragma unroll
            for (int n = 0; n < 4; ++n) {
                wmma::load_matrix_sync(fb[n], Bs + (wc * 64 + n * 16) * LDS + kk, LDS);
                #pragma unroll
                for (int e = 0; e < fb[n].num_elements; ++e)
                    fb[n].x[e] = wmma::__float_to_tf32(fb[n].x[e]);
            }
            #pragma unroll
            for (int m = 0; m < 2; ++m)
                #pragma unroll
                for (int n = 0; n < 4; ++n)
                    wmma::mma_sync(acc[m][n], fa[m], fb[n], acc[m][n]);
        }
        __syncthreads();
    }

    float* G = g_gram + (size_t)blockIdx.x * 16384;
    #pragma unroll
    for (int m = 0; m < 2; ++m)
        #pragma unroll
        for (int n = 0; n < 4; ++n)
            wmma::store_matrix_sync(G + (wr * 32 + m * 16) * 128 + wc * 64 + n * 16,
                                    acc[m][n], 128, wmma::mem_row_major);
}

// =====================================================================
// PSD reduce (fused): one thread per frequency, sum 128 pairs, log,
// block partial sums. grid 64 x 256.
// =====================================================================
__global__ __launch_bounds__(256)
void psd_reduce_kernel() {
    const int f = blockIdx.x * 256 + threadIdx.x;   // 0..16383
    float s = 0.0f;
    #pragma unroll 16
    for (int im = 0; im < NPAIR; ++im) s += g_psd[(size_t)im * KTOT + f];
    float avg = s * (1.0f / 256.0f);
    float lg = logf(avg);

    __shared__ float redl[8], reda[8];
    float sl = lg, sa = avg;
    #pragma unroll
    for (int o = 16; o > 0; o >>= 1) {
        sl += __shfl_xor_sync(0xFFFFFFFFu, sl, o);
        sa += __shfl_xor_sync(0xFFFFFFFFu, sa, o);
    }
    if ((threadIdx.x & 31) == 0) {
        redl[threadIdx.x >> 5] = sl;
        reda[threadIdx.x >> 5] = sa;
    }
    __syncthreads();
    if (threadIdx.x == 0) {
        float tl = 0.0f, ta = 0.0f;
        #pragma unroll
        for (int w = 0; w < 8; ++w) { tl += redl[w]; ta += reda[w]; }
        g_psd_part[blockIdx.x]       = tl;
        g_psd_part[128 + blockIdx.x] = ta;
    }
}

// =====================================================================
// Per-row: assemble Dist, row LSE, diag log-prob. grid 128, 128 thr.
// =====================================================================
__global__ __launch_bounds__(128)
void softmax_kernel() {
    const int i = blockIdx.x;
    const int j = threadIdx.x;

    float g = 0.0f;
    #pragma unroll 16
    for (int ks = 0; ks < GSLICES; ++ks) g += g_gram[(size_t)ks * 16384 + i * 128 + j];
    float d2 = g_norm[i] + g_norm[128 + j] - 2.0f * g;
    float dist = sqrtf(fmaxf(d2, 0.0f));

    __shared__ float red[8];
    float m = dist;
    #pragma unroll
    for (int o = 16; o > 0; o >>= 1) m = fmaxf(m, __shfl_xor_sync(0xFFFFFFFFu, m, o));
    if ((j & 31) == 0) red[j >> 5] = m;
    __syncthreads();
    float bm = fmaxf(fmaxf(red[0], red[1]), fmaxf(red[2], red[3]));
    float e = expf(dist - bm);
    #pragma unroll
    for (int o = 16; o > 0; o >>= 1) e += __shfl_xor_sync(0xFFFFFFFFu, e, o);
    if ((j & 31) == 0) red[4 + (j >> 5)] = e;
    __syncthreads();
    float bs = red[4] + red[5] + red[6] + red[7];

    if (j == i) g_rowvals[i] = dist - (bm + logf(bs));
}

// =====================================================================
// Final scalar: ce - REG * r
// =====================================================================
__global__ __launch_bounds__(128)
void final_kernel(float* __restrict__ out) {
    const int t = threadIdx.x;
    float rv = g_rowvals[t];
    float p1 = (t < 64) ? g_psd_part[t] : 0.0f;
    float p2 = (t < 64) ? g_psd_part[128 + t] : 0.0f;

    __shared__ float red[12];
    #pragma unroll
    for (int o = 16; o > 0; o >>= 1) {
        rv += __shfl_xor_sync(0xFFFFFFFFu, rv, o);
        p1 += __shfl_xor_sync(0xFFFFFFFFu, p1, o);
        p2 += __shfl_xor_sync(0xFFFFFFFFu, p2, o);
    }
    int w = t >> 5;
    if ((t & 31) == 0) { red[w] = rv; red[4 + w] = p1; red[8 + w] = p2; }
    __syncthreads();
    if (t == 0) {
        float srv = red[0] + red[1] + red[2] + red[3];
        float s1  = red[4] + red[5] + red[6] + red[7];
        float s2  = red[8] + red[9] + red[10] + red[11];
        float ce = -(srv * (1.0f / 128.0f));
        float r  = s1 * (1.0f / 16384.0f) - logf(s2 * (1.0f / 16384.0f));
        out[0] = ce - 0.1f * r;
    }
}

// =====================================================================
extern "C" void kernel_launch(void* const* d_in, const int* in_sizes, int n_in,
                              void* d_out, int out_size) {
    const float* x1 = (const float*)d_in[0];
    const float* x2 = (const float*)d_in[1];
    float* out = (float*)d_out;

    cudaFuncSetAttribute(fft_psd_kernel,
                         cudaFuncAttributeMaxDynamicSharedMemorySize, FFT_SMEM);

    fft_psd_kernel<<<NPAIR, 1024, FFT_SMEM>>>(x1, x2);
    gram_wmma_kernel<<<GSLICES, 256>>>(x1, x2);
    psd_reduce_kernel<<<64, 256>>>();
    softmax_kernel<<<128, 128>>>();
    final_kernel<<<1, 128>>>(out);
}

// round 9
// speedup vs baseline: 2.5980x; 1.3525x over previous
#include <cuda_runtime.h>
#include <math.h>
#include <stdint.h>
#include <mma.h>

using namespace nvcuda;

#define HW 128
#define NPAIR 128           // 128 packed complex images (a + i*b)
#define KTOT 16384          // HW*HW
#define GSLICES 128         // split-K slices for gram
#define GKC 128             // K per slice (per CTA)
#define LDS 36              // smem row stride (32 + 4 pad), floats

// ---- scratch (device globals: allocation-free) ----
__device__ float g_psd[NPAIR * KTOT];            // per-pair |F_a|^2+|F_b|^2 (8 MB)
__device__ float g_gram[GSLICES * 128 * 128];    // split-K gram partials (8 MB)
__device__ float g_psd_p1[8 * KTOT];             // stage-1 psd partials (512 KB)
__device__ float g_gram_p1[8 * KTOT];            // stage-1 gram partials (512 KB)
__device__ float g_norm[256];                    // row squared norms (a then b)
__device__ float g_rowvals[128];                 // diag log-prob per row
__device__ float g_psd_part[256];                // [0:64) sum(log avg), [128:192) sum(avg)

// =====================================================================
// complex helpers
// =====================================================================
__device__ __forceinline__ float2 cadd(float2 a, float2 b) { return make_float2(a.x + b.x, a.y + b.y); }
__device__ __forceinline__ float2 csub(float2 a, float2 b) { return make_float2(a.x - b.x, a.y - b.y); }
__device__ __forceinline__ float2 cmul(float2 a, float2 w) {
    return make_float2(a.x * w.x - a.y * w.y, a.x * w.y + a.y * w.x);
}

// =====================================================================
// 2D FFT of packed z = a + i*b (radix-2 DIF, 3 stages fused per exchange,
// no bit reversal). PSD via conjugate symmetry. Norms fused into load.
// One block per pair, 1024 threads.
// =====================================================================
#define FFT_SMEM ((128 * 129 + 64) * (int)sizeof(float2))

template<int S>
__device__ __forceinline__ void fft_level1(float2* d, int j, const float2* tw) {
    float2 u[8];
    #pragma unroll
    for (int k = 0; k < 8; ++k) u[k] = d[(j + 16 * k) * S];
    float2 a[8];
    #pragma unroll
    for (int k = 0; k < 4; ++k) {
        a[k]     = cadd(u[k], u[k + 4]);
        a[k + 4] = cmul(csub(u[k], u[k + 4]), tw[j + 16 * k]);
    }
    float2 w0 = tw[2 * j], w1 = tw[2 * j + 32];
    float2 b[8];
    b[0] = cadd(a[0], a[2]); b[2] = cmul(csub(a[0], a[2]), w0);
    b[1] = cadd(a[1], a[3]); b[3] = cmul(csub(a[1], a[3]), w1);
    b[4] = cadd(a[4], a[6]); b[6] = cmul(csub(a[4], a[6]), w0);
    b[5] = cadd(a[5], a[7]); b[7] = cmul(csub(a[5], a[7]), w1);
    float2 w2 = tw[4 * j];
    float2 c[8];
    #pragma unroll
    for (int k = 0; k < 8; k += 2) {
        c[k]     = cadd(b[k], b[k + 1]);
        c[k + 1] = cmul(csub(b[k], b[k + 1]), w2);
    }
    #pragma unroll
    for (int k = 0; k < 8; ++k) d[(j + 16 * k) * S] = c[k];
}

template<int S>
__device__ __forceinline__ void fft_level2(float2* d, int m, int j, const float2* tw) {
    const int p = 16 * m + j;
    float2 u[8];
    #pragma unroll
    for (int k = 0; k < 8; ++k) u[k] = d[(p + 2 * k) * S];
    float2 a[8];
    #pragma unroll
    for (int k = 0; k < 4; ++k) {
        a[k]     = cadd(u[k], u[k + 4]);
        a[k + 4] = cmul(csub(u[k], u[k + 4]), tw[8 * j + 16 * k]);
    }
    float2 w0 = tw[16 * j], w1 = tw[16 * j + 32];
    float2 b[8];
    b[0] = cadd(a[0], a[2]); b[2] = cmul(csub(a[0], a[2]), w0);
    b[1] = cadd(a[1], a[3]); b[3] = cmul(csub(a[1], a[3]), w1);
    b[4] = cadd(a[4], a[6]); b[6] = cmul(csub(a[4], a[6]), w0);
    b[5] = cadd(a[5], a[7]); b[7] = cmul(csub(a[5], a[7]), w1);
    float2 w2 = tw[32 * j];
    float2 c[8];
    #pragma unroll
    for (int k = 0; k < 8; k += 2) {
        c[k]     = cadd(b[k], b[k + 1]);
        c[k + 1] = cmul(csub(b[k], b[k + 1]), w2);
    }
    #pragma unroll
    for (int k = 0; k < 8; ++k) d[(p + 2 * k) * S] = c[k];
}

template<int S>
__device__ __forceinline__ void fft_level3(float2* d, int m) {
    float2 u = d[(2 * m) * S];
    float2 v = d[(2 * m + 1) * S];
    d[(2 * m) * S]     = cadd(u, v);
    d[(2 * m + 1) * S] = csub(u, v);
}

__global__ __launch_bounds__(1024, 1)
void fft_psd_kernel(const float* __restrict__ x1, const float* __restrict__ x2) {
    extern __shared__ float2 sm[];
    float2* data = sm;                 // 128 * 129
    float2* tw   = sm + 128 * 129;     // 64 twiddles
    __shared__ int   msk[128];
    __shared__ float redn[64];

    const int t    = threadIdx.x;
    const int line = t & 127;
    const int sub  = t >> 7;
    const int img  = blockIdx.x;
    const float* sa = x1 + (size_t)img * KTOT;
    const float* sb = x2 + (size_t)img * KTOT;

    if (t < 64) {
        float s, c;
        sincosf(-6.283185307179586f * (float)t * (1.0f / 128.0f), &s, &c);
        tw[t] = make_float2(c, s);
    }
    if (t < 128) {
        unsigned r = __brev((unsigned)t) >> 25;
        unsigned n = (128u - r) & 127u;
        msk[t] = (int)(__brev(n) >> 25);
    }

    float na = 0.0f, nb = 0.0f;
    #pragma unroll
    for (int idx = t; idx < KTOT; idx += 1024) {
        float va = sa[idx];
        float vb = sb[idx];
        na += va * va;
        nb += vb * vb;
        data[(idx >> 7) * 129 + (idx & 127)] = make_float2(va, vb);
    }
    #pragma unroll
    for (int o = 16; o > 0; o >>= 1) {
        na += __shfl_xor_sync(0xFFFFFFFFu, na, o);
        nb += __shfl_xor_sync(0xFFFFFFFFu, nb, o);
    }
    if ((t & 31) == 0) { redn[t >> 5] = na; redn[32 + (t >> 5)] = nb; }
    __syncthreads();
    if (t == 0) {
        float ta = 0.0f, tb = 0.0f;
        #pragma unroll
        for (int w = 0; w < 32; ++w) { ta += redn[w]; tb += redn[32 + w]; }
        g_norm[img] = ta;
        g_norm[128 + img] = tb;
    }

    {   // rows
        float2* d = data + line * 129;
        #pragma unroll
        for (int i = 0; i < 2; ++i) fft_level1<1>(d, 2 * sub + i, tw);
        __syncthreads();
        #pragma unroll
        for (int i = 0; i < 2; ++i) { int g = 2 * sub + i; fft_level2<1>(d, g >> 1, g & 1, tw); }
        __syncthreads();
        #pragma unroll
        for (int i = 0; i < 8; ++i) fft_level3<1>(d, 8 * sub + i);
        __syncthreads();
    }
    {   // cols
        float2* d = data + line;
        #pragma unroll
        for (int i = 0; i < 2; ++i) fft_level1<129>(d, 2 * sub + i, tw);
        __syncthreads();
        #pragma unroll
        for (int i = 0; i < 2; ++i) { int g = 2 * sub + i; fft_level2<129>(d, g >> 1, g & 1, tw); }
        __syncthreads();
        #pragma unroll
        for (int i = 0; i < 8; ++i) fft_level3<129>(d, 8 * sub + i);
        __syncthreads();
    }

    float* dst = g_psd + (size_t)img * KTOT;
    #pragma unroll
    for (int idx = t; idx < KTOT; idx += 1024) {
        int i = idx >> 7, j = idx & 127;
        float2 z1 = data[i * 129 + j];
        float2 z2 = data[msk[i] * 129 + msk[j]];
        dst[idx] = 0.5f * (z1.x * z1.x + z1.y * z1.y + z2.x * z2.x + z2.y * z2.y);
    }
}

// =====================================================================
// Gram via warp-level wmma tf32 (m16n16k8). G = A * B^T.
// One CTA per K-slice of 128; 8 warps in 4x2 grid, each 32x64 of output.
// =====================================================================
typedef wmma::fragment<wmma::matrix_a, 16, 16, 8, wmma::precision::tf32, wmma::row_major> AFrag;
typedef wmma::fragment<wmma::matrix_b, 16, 16, 8, wmma::precision::tf32, wmma::col_major> BFrag;
typedef wmma::fragment<wmma::accumulator, 16, 16, 8, float> CFrag;

__global__ __launch_bounds__(256)
void gram_wmma_kernel(const float* __restrict__ A, const float* __restrict__ B) {
    __shared__ float As[128 * LDS];
    __shared__ float Bs[128 * LDS];

    const int tid = threadIdx.x;
    const int wid = tid >> 5;
    const int wr  = wid >> 1;
    const int wc  = wid & 1;
    const int k0  = blockIdx.x * GKC;

    CFrag acc[2][4];
    #pragma unroll
    for (int m = 0; m < 2; ++m)
        #pragma unroll
        for (int n = 0; n < 4; ++n) wmma::fill_fragment(acc[m][n], 0.0f);

    for (int kc = 0; kc < GKC; kc += 32) {
        #pragma unroll
        for (int idx = tid; idx < 1024; idx += 256) {
            int row = idx >> 3;
            int q   = idx & 7;
            float4 va = *(const float4*)(A + (size_t)row * KTOT + k0 + kc + q * 4);
            float4 vb = *(const float4*)(B + (size_t)row * KTOT + k0 + kc + q * 4);
            *(float4*)(As + row * LDS + q * 4) = va;
            *(float4*)(Bs + row * LDS + q * 4) = vb;
        }
        __syncthreads();
        #pragma unroll
        for (int kk = 0; kk < 32; kk += 8) {
            AFrag fa[2];
            BFrag fb[4];
            #pragma unroll
            for (int m = 0; m < 2; ++m) {
                wmma::load_matrix_sync(fa[m], As + (wr * 32 + m * 16) * LDS + kk, LDS);
                #pragma unroll
                for (int e = 0; e < fa[m].num_elements; ++e)
                    fa[m].x[e] = wmma::__float_to_tf32(fa[m].x[e]);
            }
            #pragma unroll
            for (int n = 0; n < 4; ++n) {
                wmma::load_matrix_sync(fb[n], Bs + (wc * 64 + n * 16) * LDS + kk, LDS);
                #pragma unroll
                for (int e = 0; e < fb[n].num_elements; ++e)
                    fb[n].x[e] = wmma::__float_to_tf32(fb[n].x[e]);
            }
            #pragma unroll
            for (int m = 0; m < 2; ++m)
                #pragma unroll
                for (int n = 0; n < 4; ++n)
                    wmma::mma_sync(acc[m][n], fa[m], fb[n], acc[m][n]);
        }
        __syncthreads();
    }

    float* G = g_gram + (size_t)blockIdx.x * 16384;
    #pragma unroll
    for (int m = 0; m < 2; ++m)
        #pragma unroll
        for (int n = 0; n < 4; ++n)
            wmma::store_matrix_sync(G + (wr * 32 + m * 16) * 128 + wc * 64 + n * 16,
                                    acc[m][n], 128, wmma::mem_row_major);
}

// =====================================================================
// Stage-1 reduction (both 8 MB buffers): grid (64, 8, 2) x 256 thr.
// z=0: sum 16 images of g_psd;  z=1: sum 16 slices of g_gram.
// 262K threads total -> DRAM-BW-bound, not latency-bound.
// =====================================================================
__global__ __launch_bounds__(256)
void reduce_stage1_kernel() {
    const int f = blockIdx.x * 256 + threadIdx.x;       // 0..16383
    const float* src = blockIdx.z ? g_gram : g_psd;
    float* dst       = blockIdx.z ? g_gram_p1 : g_psd_p1;
    const int base = blockIdx.y * 16;
    float s = 0.0f;
    #pragma unroll
    for (int im = 0; im < 16; ++im) s += src[(size_t)(base + im) * KTOT + f];
    dst[(size_t)blockIdx.y * KTOT + f] = s;
}

// =====================================================================
// PSD stage 2: combine 8 partials, log, block partial sums. grid 64 x 256.
// =====================================================================
__global__ __launch_bounds__(256)
void psd_stage2_kernel() {
    const int f = blockIdx.x * 256 + threadIdx.x;
    float s = 0.0f;
    #pragma unroll
    for (int ig = 0; ig < 8; ++ig) s += g_psd_p1[(size_t)ig * KTOT + f];
    float avg = s * (1.0f / 256.0f);
    float lg = logf(avg);

    __shared__ float redl[8], reda[8];
    float sl = lg, sa = avg;
    #pragma unroll
    for (int o = 16; o > 0; o >>= 1) {
        sl += __shfl_xor_sync(0xFFFFFFFFu, sl, o);
        sa += __shfl_xor_sync(0xFFFFFFFFu, sa, o);
    }
    if ((threadIdx.x & 31) == 0) {
        redl[threadIdx.x >> 5] = sl;
        reda[threadIdx.x >> 5] = sa;
    }
    __syncthreads();
    if (threadIdx.x == 0) {
        float tl = 0.0f, ta = 0.0f;
        #pragma unroll
        for (int w = 0; w < 8; ++w) { tl += redl[w]; ta += reda[w]; }
        g_psd_part[blockIdx.x]       = tl;
        g_psd_part[128 + blockIdx.x] = ta;
    }
}

// =====================================================================
// Per-row: combine 8 gram partials, Dist, LSE, diag log-prob.
// grid 128 x 128 thr (reads only 512 KB now).
// =====================================================================
__global__ __launch_bounds__(128)
void dist_softmax_kernel() {
    const int i = blockIdx.x;
    const int j = threadIdx.x;

    float g = 0.0f;
    #pragma unroll
    for (int ig = 0; ig < 8; ++ig) g += g_gram_p1[(size_t)ig * KTOT + i * 128 + j];
    float d2 = g_norm[i] + g_norm[128 + j] - 2.0f * g;
    float dist = sqrtf(fmaxf(d2, 0.0f));

    __shared__ float red[8];
    float m = dist;
    #pragma unroll
    for (int o = 16; o > 0; o >>= 1) m = fmaxf(m, __shfl_xor_sync(0xFFFFFFFFu, m, o));
    if ((j & 31) == 0) red[j >> 5] = m;
    __syncthreads();
    float bm = fmaxf(fmaxf(red[0], red[1]), fmaxf(red[2], red[3]));
    float e = expf(dist - bm);
    #pragma unroll
    for (int o = 16; o > 0; o >>= 1) e += __shfl_xor_sync(0xFFFFFFFFu, e, o);
    if ((j & 31) == 0) red[4 + (j >> 5)] = e;
    __syncthreads();
    float bs = red[4] + red[5] + red[6] + red[7];

    if (j == i) g_rowvals[i] = dist - (bm + logf(bs));
}

// =====================================================================
// Final scalar: ce - REG * r
// =====================================================================
__global__ __launch_bounds__(128)
void final_kernel(float* __restrict__ out) {
    const int t = threadIdx.x;
    float rv = g_rowvals[t];
    float p1 = (t < 64) ? g_psd_part[t] : 0.0f;
    float p2 = (t < 64) ? g_psd_part[128 + t] : 0.0f;

    __shared__ float red[12];
    #pragma unroll
    for (int o = 16; o > 0; o >>= 1) {
        rv += __shfl_xor_sync(0xFFFFFFFFu, rv, o);
        p1 += __shfl_xor_sync(0xFFFFFFFFu, p1, o);
        p2 += __shfl_xor_sync(0xFFFFFFFFu, p2, o);
    }
    int w = t >> 5;
    if ((t & 31) == 0) { red[w] = rv; red[4 + w] = p1; red[8 + w] = p2; }
    __syncthreads();
    if (t == 0) {
        float srv = red[0] + red[1] + red[2] + red[3];
        float s1  = red[4] + red[5] + red[6] + red[7];
        float s2  = red[8] + red[9] + red[10] + red[11];
        float ce = -(srv * (1.0f / 128.0f));
        float r  = s1 * (1.0f / 16384.0f) - logf(s2 * (1.0f / 16384.0f));
        out[0] = ce - 0.1f * r;
    }
}

// =====================================================================
extern "C" void kernel_launch(void* const* d_in, const int* in_sizes, int n_in,
                              void* d_out, int out_size) {
    const float* x1 = (const float*)d_in[0];
    const float* x2 = (const float*)d_in[1];
    float* out = (float*)d_out;

    cudaFuncSetAttribute(fft_psd_kernel,
                         cudaFuncAttributeMaxDynamicSharedMemorySize, FFT_SMEM);

    fft_psd_kernel<<<NPAIR, 1024, FFT_SMEM>>>(x1, x2);
    gram_wmma_kernel<<<GSLICES, 256>>>(x1, x2);
    reduce_stage1_kernel<<<dim3(64, 8, 2), 256>>>();
    psd_stage2_kernel<<<64, 256>>>();
    dist_softmax_kernel<<<128, 128>>>();
    final_kernel<<<1, 128>>>(out);
}

// round 10
// speedup vs baseline: 2.7779x; 1.0692x over previous
#include <cuda_runtime.h>
#include <math.h>
#include <stdint.h>
#include <mma.h>

using namespace nvcuda;

#define HW 128
#define NPAIR 128           // 128 packed complex images (a + i*b)
#define KTOT 16384          // HW*HW
#define GSLICES 128         // split-K slices for gram
#define GKC 128             // K per slice (per CTA)
#define LDS 36              // smem row stride (32 + 4 pad), floats

// ---- scratch (device globals: allocation-free) ----
__device__ float g_psd[NPAIR * KTOT];            // per-pair |F_a|^2+|F_b|^2 (8 MB)
__device__ float g_gram[GSLICES * 128 * 128];    // split-K gram partials (8 MB)
__device__ float g_psd_p1[8 * KTOT];             // stage-1 psd partials (512 KB)
__device__ float g_gram_p1[8 * KTOT];            // stage-1 gram partials (512 KB)
__device__ float g_norm[256];                    // row squared norms (a then b)
__device__ float g_rowvals[128];                 // diag log-prob per row
__device__ float g_psd_part[256];                // [0:64) sum(log avg), [128:192) sum(avg)

// =====================================================================
// complex helpers
// =====================================================================
__device__ __forceinline__ float2 cadd(float2 a, float2 b) { return make_float2(a.x + b.x, a.y + b.y); }
__device__ __forceinline__ float2 csub(float2 a, float2 b) { return make_float2(a.x - b.x, a.y - b.y); }
__device__ __forceinline__ float2 cmul(float2 a, float2 w) {
    return make_float2(a.x * w.x - a.y * w.y, a.x * w.y + a.y * w.x);
}

// =====================================================================
// 2D FFT of packed z = a + i*b. Radix-2 DIF, 7 stages split 4+3:
// levelA (h=64,32,16,8) on points j0+8m held in registers, one smem
// exchange, levelB (h=4,2,1) on 8-point contiguous blocks. No bit
// reversal (PSD stats permutation-invariant). PSD via conjugate
// symmetry. Norms fused into the (float4-vectorized) load.
// One block per pair, 1024 threads (line = t&127, j0 = t>>7).
// =====================================================================
#define FFT_SMEM ((128 * 129 + 64) * (int)sizeof(float2))

// levelA: stages h=64,32,16,8 on points (j0 + 8m), m = 0..15, j0 in [0,8)
template<int S>
__device__ __forceinline__ void fft_levelA(float2* d, int j0, const float2* tw) {
    float2 u[16];
    #pragma unroll
    for (int m = 0; m < 16; ++m) u[m] = d[(j0 + 8 * m) * S];
    // h=64: pairs (m, m+8), twiddle tw[j0+8m]
    float2 a[16];
    #pragma unroll
    for (int m = 0; m < 8; ++m) {
        a[m]     = cadd(u[m], u[m + 8]);
        a[m + 8] = cmul(csub(u[m], u[m + 8]), tw[j0 + 8 * m]);
    }
    // h=32: within halves, pairs (m, m+4), twiddle tw[2*(j0+8m)]
    float2 b[16];
    #pragma unroll
    for (int g = 0; g < 2; ++g) {
        #pragma unroll
        for (int m = 0; m < 4; ++m) {
            int lo = g * 8 + m;
            float2 w = tw[2 * (j0 + 8 * m)];
            b[lo]     = cadd(a[lo], a[lo + 4]);
            b[lo + 4] = cmul(csub(a[lo], a[lo + 4]), w);
        }
    }
    // h=16: groups of 4, pairs (m, m+2), twiddle tw[4*j0 + 32*m]
    float2 c[16];
    #pragma unroll
    for (int g = 0; g < 4; ++g) {
        #pragma unroll
        for (int m = 0; m < 2; ++m) {
            int lo = g * 4 + m;
            float2 w = tw[4 * j0 + 32 * m];
            c[lo]     = cadd(b[lo], b[lo + 2]);
            c[lo + 2] = cmul(csub(b[lo], b[lo + 2]), w);
        }
    }
    // h=8: adjacent pairs, twiddle tw[8*j0]
    float2 w8 = tw[8 * j0];
    #pragma unroll
    for (int m = 0; m < 16; m += 2) {
        float2 t0 = cadd(c[m], c[m + 1]);
        float2 t1 = cmul(csub(c[m], c[m + 1]), w8);
        d[(j0 + 8 * m) * S]       = t0;
        d[(j0 + 8 * (m + 1)) * S] = t1;
    }
}

// levelB: stages h=4,2,1 on 8 contiguous points starting at q (q % 8 == 0)
template<int S>
__device__ __forceinline__ void fft_levelB(float2* d, int q, const float2* tw) {
    float2 v[8];
    #pragma unroll
    for (int k = 0; k < 8; ++k) v[k] = d[(q + k) * S];
    // h=4: pairs (k, k+4), twiddle tw[16k]
    float2 a[8];
    #pragma unroll
    for (int k = 0; k < 4; ++k) {
        a[k]     = cadd(v[k], v[k + 4]);
        a[k + 4] = cmul(csub(v[k], v[k + 4]), tw[16 * k]);
    }
    // h=2: within halves, pairs (k, k+2), twiddle tw[32k]
    float2 b[8];
    #pragma unroll
    for (int g = 0; g < 2; ++g) {
        #pragma unroll
        for (int k = 0; k < 2; ++k) {
            int lo = g * 4 + k;
            b[lo]     = cadd(a[lo], a[lo + 2]);
            b[lo + 2] = cmul(csub(a[lo], a[lo + 2]), tw[32 * k]);
        }
    }
    // h=1: adjacent pairs, twiddle 1
    #pragma unroll
    for (int k = 0; k < 8; k += 2) {
        d[(q + k) * S]     = cadd(b[k], b[k + 1]);
        d[(q + k + 1) * S] = csub(b[k], b[k + 1]);
    }
}

__global__ __launch_bounds__(1024, 1)
void fft_psd_kernel(const float* __restrict__ x1, const float* __restrict__ x2) {
    extern __shared__ float2 sm[];
    float2* data = sm;                 // 128 * 129
    float2* tw   = sm + 128 * 129;     // 64 twiddles
    __shared__ int   msk[128];
    __shared__ float redn[64];

    const int t    = threadIdx.x;
    const int line = t & 127;
    const int j0   = t >> 7;           // 0..7
    const int img  = blockIdx.x;
    const float* sa = x1 + (size_t)img * KTOT;
    const float* sb = x2 + (size_t)img * KTOT;

    if (t < 64) {
        float s, c;
        sincosf(-6.283185307179586f * (float)t * (1.0f / 128.0f), &s, &c);
        tw[t] = make_float2(c, s);
    }
    if (t < 128) {
        unsigned r = __brev((unsigned)t) >> 25;
        unsigned n = (128u - r) & 127u;
        msk[t] = (int)(__brev(n) >> 25);
    }

    // float4-vectorized load + fused norms
    float na = 0.0f, nb = 0.0f;
    #pragma unroll
    for (int v = t; v < 4096; v += 1024) {
        float4 va = ((const float4*)sa)[v];
        float4 vb = ((const float4*)sb)[v];
        na += va.x * va.x + va.y * va.y + va.z * va.z + va.w * va.w;
        nb += vb.x * vb.x + vb.y * vb.y + vb.z * vb.z + vb.w * vb.w;
        int i = v >> 5;
        int j = (v & 31) * 4;
        float2* base = data + i * 129 + j;
        base[0] = make_float2(va.x, vb.x);
        base[1] = make_float2(va.y, vb.y);
        base[2] = make_float2(va.z, vb.z);
        base[3] = make_float2(va.w, vb.w);
    }
    #pragma unroll
    for (int o = 16; o > 0; o >>= 1) {
        na += __shfl_xor_sync(0xFFFFFFFFu, na, o);
        nb += __shfl_xor_sync(0xFFFFFFFFu, nb, o);
    }
    if ((t & 31) == 0) { redn[t >> 5] = na; redn[32 + (t >> 5)] = nb; }
    __syncthreads();   // covers data, tw, msk, redn
    if (t == 0) {
        float ta = 0.0f, tb = 0.0f;
        #pragma unroll
        for (int w = 0; w < 32; ++w) { ta += redn[w]; tb += redn[32 + w]; }
        g_norm[img] = ta;
        g_norm[128 + img] = tb;
    }

    {   // pass 1: row FFTs (stride 1)
        float2* d = data + line * 129;
        fft_levelA<1>(d, j0, tw);
        __syncthreads();
        fft_levelB<1>(d, j0 * 16, tw);
        fft_levelB<1>(d, j0 * 16 + 8, tw);
        __syncthreads();
    }
    {   // pass 2: column FFTs (stride 129)
        float2* d = data + line;
        fft_levelA<129>(d, j0, tw);
        __syncthreads();
        fft_levelB<129>(d, j0 * 16, tw);
        fft_levelB<129>(d, j0 * 16 + 8, tw);
        __syncthreads();
    }

    // |F_a|^2 + |F_b|^2 via conjugate-symmetry unpacking
    float* dst = g_psd + (size_t)img * KTOT;
    #pragma unroll
    for (int idx = t; idx < KTOT; idx += 1024) {
        int i = idx >> 7, j = idx & 127;
        float2 z1 = data[i * 129 + j];
        float2 z2 = data[msk[i] * 129 + msk[j]];
        dst[idx] = 0.5f * (z1.x * z1.x + z1.y * z1.y + z2.x * z2.x + z2.y * z2.y);
    }
}

// =====================================================================
// Gram via warp-level wmma tf32 (m16n16k8). G = A * B^T.
// One CTA per K-slice of 128; 8 warps in 4x2 grid, each 32x64 of output.
// =====================================================================
typedef wmma::fragment<wmma::matrix_a, 16, 16, 8, wmma::precision::tf32, wmma::row_major> AFrag;
typedef wmma::fragment<wmma::matrix_b, 16, 16, 8, wmma::precision::tf32, wmma::col_major> BFrag;
typedef wmma::fragment<wmma::accumulator, 16, 16, 8, float> CFrag;

__global__ __launch_bounds__(256)
void gram_wmma_kernel(const float* __restrict__ A, const float* __restrict__ B) {
    __shared__ float As[128 * LDS];
    __shared__ float Bs[128 * LDS];

    const int tid = threadIdx.x;
    const int wid = tid >> 5;
    const int wr  = wid >> 1;
    const int wc  = wid & 1;
    const int k0  = blockIdx.x * GKC;

    CFrag acc[2][4];
    #pragma unroll
    for (int m = 0; m < 2; ++m)
        #pragma unroll
        for (int n = 0; n < 4; ++n) wmma::fill_fragment(acc[m][n], 0.0f);

    for (int kc = 0; kc < GKC; kc += 32) {
        #pragma unroll
        for (int idx = tid; idx < 1024; idx += 256) {
            int row = idx >> 3;
            int q   = idx & 7;
            float4 va = *(const float4*)(A + (size_t)row * KTOT + k0 + kc + q * 4);
            float4 vb = *(const float4*)(B + (size_t)row * KTOT + k0 + kc + q * 4);
            *(float4*)(As + row * LDS + q * 4) = va;
            *(float4*)(Bs + row * LDS + q * 4) = vb;
        }
        __syncthreads();
        #pragma unroll
        for (int kk = 0; kk < 32; kk += 8) {
            AFrag fa[2];
            BFrag fb[4];
            #pragma unroll
            for (int m = 0; m < 2; ++m) {
                wmma::load_matrix_sync(fa[m], As + (wr * 32 + m * 16) * LDS + kk, LDS);
                #pragma unroll
                for (int e = 0; e < fa[m].num_elements; ++e)
                    fa[m].x[e] = wmma::__float_to_tf32(fa[m].x[e]);
            }
            #pragma unroll
            for (int n = 0; n < 4; ++n) {
                wmma::load_matrix_sync(fb[n], Bs + (wc * 64 + n * 16) * LDS + kk, LDS);
                #pragma unroll
                for (int e = 0; e < fb[n].num_elements; ++e)
                    fb[n].x[e] = wmma::__float_to_tf32(fb[n].x[e]);
            }
            #pragma unroll
            for (int m = 0; m < 2; ++m)
                #pragma unroll
                for (int n = 0; n < 4; ++n)
                    wmma::mma_sync(acc[m][n], fa[m], fb[n], acc[m][n]);
        }
        __syncthreads();
    }

    float* G = g_gram + (size_t)blockIdx.x * 16384;
    #pragma unroll
    for (int m = 0; m < 2; ++m)
        #pragma unroll
        for (int n = 0; n < 4; ++n)
            wmma::store_matrix_sync(G + (wr * 32 + m * 16) * 128 + wc * 64 + n * 16,
                                    acc[m][n], 128, wmma::mem_row_major);
}

// =====================================================================
// Stage-1 reduction (both 8 MB buffers): grid (64, 8, 2) x 256 thr.
// z=0: sum 16 images of g_psd;  z=1: sum 16 slices of g_gram.
// =====================================================================
__global__ __launch_bounds__(256)
void reduce_stage1_kernel() {
    const int f = blockIdx.x * 256 + threadIdx.x;       // 0..16383
    const float* src = blockIdx.z ? g_gram : g_psd;
    float* dst       = blockIdx.z ? g_gram_p1 : g_psd_p1;
    const int base = blockIdx.y * 16;
    float s = 0.0f;
    #pragma unroll
    for (int im = 0; im < 16; ++im) s += src[(size_t)(base + im) * KTOT + f];
    dst[(size_t)blockIdx.y * KTOT + f] = s;
}

// =====================================================================
// Tail (fused): blocks 0..63 = PSD stage 2 (combine 8 partials, log,
// block partial sums); blocks 64..127 = dist+softmax, 2 rows per block.
// =====================================================================
__global__ __launch_bounds__(256)
void tail_kernel() {
    const int b = blockIdx.x;
    const int t = threadIdx.x;

    if (b < 64) {
        // ---- PSD stage 2 ----
        const int f = b * 256 + t;
        float s = 0.0f;
        #pragma unroll
        for (int ig = 0; ig < 8; ++ig) s += g_psd_p1[(size_t)ig * KTOT + f];
        float avg = s * (1.0f / 256.0f);
        float lg = logf(avg);

        __shared__ float redl[8], reda[8];
        float sl = lg, sa = avg;
        #pragma unroll
        for (int o = 16; o > 0; o >>= 1) {
            sl += __shfl_xor_sync(0xFFFFFFFFu, sl, o);
            sa += __shfl_xor_sync(0xFFFFFFFFu, sa, o);
        }
        if ((t & 31) == 0) { redl[t >> 5] = sl; reda[t >> 5] = sa; }
        __syncthreads();
        if (t == 0) {
            float tl = 0.0f, ta = 0.0f;
            #pragma unroll
            for (int w = 0; w < 8; ++w) { tl += redl[w]; ta += reda[w]; }
            g_psd_part[b]       = tl;
            g_psd_part[128 + b] = ta;
        }
    } else {
        // ---- dist + softmax, two rows per block ----
        const int half = t >> 7;                 // 0 or 1
        const int i = (b - 64) * 2 + half;       // row 0..127
        const int j = t & 127;
        const int w = t >> 5;                    // warp 0..7 (0-3 half0, 4-7 half1)

        float g = 0.0f;
        #pragma unroll
        for (int ig = 0; ig < 8; ++ig) g += g_gram_p1[(size_t)ig * KTOT + i * 128 + j];
        float d2 = g_norm[i] + g_norm[128 + j] - 2.0f * g;
        float dist = sqrtf(fmaxf(d2, 0.0f));

        __shared__ float red[16];
        float m = dist;
        #pragma unroll
        for (int o = 16; o > 0; o >>= 1) m = fmaxf(m, __shfl_xor_sync(0xFFFFFFFFu, m, o));
        if ((t & 31) == 0) red[w] = m;
        __syncthreads();
        float bm = fmaxf(fmaxf(red[half * 4 + 0], red[half * 4 + 1]),
                         fmaxf(red[half * 4 + 2], red[half * 4 + 3]));
        float e = expf(dist - bm);
        #pragma unroll
        for (int o = 16; o > 0; o >>= 1) e += __shfl_xor_sync(0xFFFFFFFFu, e, o);
        if ((t & 31) == 0) red[8 + w] = e;
        __syncthreads();
        float bs = red[8 + half * 4 + 0] + red[8 + half * 4 + 1]
                 + red[8 + half * 4 + 2] + red[8 + half * 4 + 3];

        if (j == i) g_rowvals[i] = dist - (bm + logf(bs));
    }
}

// =====================================================================
// Final scalar: ce - REG * r
// =====================================================================
__global__ __launch_bounds__(128)
void final_kernel(float* __restrict__ out) {
    const int t = threadIdx.x;
    float rv = g_rowvals[t];
    float p1 = (t < 64) ? g_psd_part[t] : 0.0f;
    float p2 = (t < 64) ? g_psd_part[128 + t] : 0.0f;

    __shared__ float red[12];
    #pragma unroll
    for (int o = 16; o > 0; o >>= 1) {
        rv += __shfl_xor_sync(0xFFFFFFFFu, rv, o);
        p1 += __shfl_xor_sync(0xFFFFFFFFu, p1, o);
        p2 += __shfl_xor_sync(0xFFFFFFFFu, p2, o);
    }
    int w = t >> 5;
    if ((t & 31) == 0) { red[w] = rv; red[4 + w] = p1; red[8 + w] = p2; }
    __syncthreads();
    if (t == 0) {
        float srv = red[0] + red[1] + red[2] + red[3];
        float s1  = red[4] + red[5] + red[6] + red[7];
        float s2  = red[8] + red[9] + red[10] + red[11];
        float ce = -(srv * (1.0f / 128.0f));
        float r  = s1 * (1.0f / 16384.0f) - logf(s2 * (1.0f / 16384.0f));
        out[0] = ce - 0.1f * r;
    }
}

// =====================================================================
extern "C" void kernel_launch(void* const* d_in, const int* in_sizes, int n_in,
                              void* d_out, int out_size) {
    const float* x1 = (const float*)d_in[0];
    const float* x2 = (const float*)d_in[1];
    float* out = (float*)d_out;

    cudaFuncSetAttribute(fft_psd_kernel,
                         cudaFuncAttributeMaxDynamicSharedMemorySize, FFT_SMEM);

    fft_psd_kernel<<<NPAIR, 1024, FFT_SMEM>>>(x1, x2);
    gram_wmma_kernel<<<GSLICES, 256>>>(x1, x2);
    reduce_stage1_kernel<<<dim3(64, 8, 2), 256>>>();
    tail_kernel<<<128, 256>>>();
    final_kernel<<<1, 128>>>(out);
}